// round 1
// baseline (speedup 1.0000x reference)
#include <cuda_runtime.h>
#include <cuda_bf16.h>
#include <cstdint>

// Problem constants
#define BATCH 2
#define SLEN  2048
#define DMODEL 4096
#define NHEAD 32
#define NKVH  8
#define HDIM  128
#define NTOK  (BATCH*SLEN)          // 4096
#define QKVW  6144                  // 4096 q + 1024 k + 1024 v
#define ATT_SCALE 0.08838834764831845f

// Scratch (allocation-free rule: __device__ globals)
__device__ float g_qkv[(size_t)NTOK * QKVW];    // [tok][6144] : q|k|v per token
__device__ float g_att[(size_t)NTOK * DMODEL];  // [tok][4096] : attention output

// ---------------------------------------------------------------------------
// SGEMM: C[M][N] = A[M][K] * B[N][K]^T   (both row-major, K contiguous)
// 128x128 tile, BK=8, 256 threads, 8x8 microtile.
// M,K fixed multiples of 128/8; grid = (N/128, M/128).
// ---------------------------------------------------------------------------
__global__ __launch_bounds__(256) void sgemm_tn(const float* __restrict__ A,
                                                const float* __restrict__ Bm,
                                                float* __restrict__ Cc,
                                                int K, int ldc)
{
    __shared__ float As[8][128];
    __shared__ float Bs[8][128];
    const int tid = threadIdx.x;
    const int tx = tid & 15;        // n dir (16)
    const int ty = tid >> 4;        // m dir (16)
    const float* Ab = A  + (size_t)(blockIdx.y * 128) * K;
    const float* Bb = Bm + (size_t)(blockIdx.x * 128) * K;
    const int lrow = tid >> 1;          // 0..127
    const int lcol = (tid & 1) << 2;    // 0 or 4

    float acc[8][8];
#pragma unroll
    for (int i = 0; i < 8; i++)
#pragma unroll
        for (int j = 0; j < 8; j++) acc[i][j] = 0.f;

    for (int k0 = 0; k0 < K; k0 += 8) {
        float4 av = *(const float4*)(Ab + (size_t)lrow * K + k0 + lcol);
        float4 bv = *(const float4*)(Bb + (size_t)lrow * K + k0 + lcol);
        As[lcol + 0][lrow] = av.x;
        As[lcol + 1][lrow] = av.y;
        As[lcol + 2][lrow] = av.z;
        As[lcol + 3][lrow] = av.w;
        Bs[lcol + 0][lrow] = bv.x;
        Bs[lcol + 1][lrow] = bv.y;
        Bs[lcol + 2][lrow] = bv.z;
        Bs[lcol + 3][lrow] = bv.w;
        __syncthreads();
#pragma unroll
        for (int kk = 0; kk < 8; kk++) {
            float a[8], b[8];
            *(float4*)&a[0] = *(const float4*)&As[kk][ty * 8];
            *(float4*)&a[4] = *(const float4*)&As[kk][ty * 8 + 4];
            *(float4*)&b[0] = *(const float4*)&Bs[kk][tx * 8];
            *(float4*)&b[4] = *(const float4*)&Bs[kk][tx * 8 + 4];
#pragma unroll
            for (int i = 0; i < 8; i++)
#pragma unroll
                for (int j = 0; j < 8; j++)
                    acc[i][j] = fmaf(a[i], b[j], acc[i][j]);
        }
        __syncthreads();
    }

    float* Cp = Cc + (size_t)(blockIdx.y * 128 + ty * 8) * ldc + blockIdx.x * 128 + tx * 8;
#pragma unroll
    for (int i = 0; i < 8; i++) {
        *(float4*)(Cp + (size_t)i * ldc)     = make_float4(acc[i][0], acc[i][1], acc[i][2], acc[i][3]);
        *(float4*)(Cp + (size_t)i * ldc + 4) = make_float4(acc[i][4], acc[i][5], acc[i][6], acc[i][7]);
    }
}

// ---------------------------------------------------------------------------
// RoPE, interleaved pairs (2p, 2p+1), applied in-place to q (heads 0..31)
// and k (heads 32..39 -> kv heads 0..7) portions of g_qkv.
// ---------------------------------------------------------------------------
__global__ void rope_kernel(float* __restrict__ qkv,
                            const float* __restrict__ cosp,
                            const float* __restrict__ sinp)
{
    int idx = blockIdx.x * 256 + threadIdx.x;            // NTOK*40*64 threads
    if (idx >= NTOK * 40 * 64) return;
    int p  = idx & 63;
    int h2 = (idx >> 6) % 40;
    int t  = idx / (64 * 40);                            // token index = b*S + s
    float c  = cosp[(size_t)t * 64 + p];
    float sn = sinp[(size_t)t * 64 + p];
    size_t base = (size_t)t * QKVW + (h2 < 32 ? h2 * HDIM : 4096 + (h2 - 32) * HDIM) + 2 * p;
    float t0 = qkv[base], t1 = qkv[base + 1];
    qkv[base]     = t0 * c - t1 * sn;
    qkv[base + 1] = t0 * sn + t1 * c;
}

// ---------------------------------------------------------------------------
// Flash attention (fp32, causal, GQA 4:1).
// Block = (qtile of 64 queries, head, batch). 256 threads (16x16).
// S microtile 4x4, O microtile 4x8. Online softmax; shuffle row-reduce over tx.
// Dynamic smem: Qs[128][64] Ks[128][64] Vs[64][128] Ps[64][64] = 112 KB.
// ---------------------------------------------------------------------------
__global__ __launch_bounds__(256) void flash_kernel(const float* __restrict__ qkv,
                                                    float* __restrict__ outp)
{
    extern __shared__ float sm[];
    float* Qs = sm;            // [d][i] 128x64
    float* Ks = sm + 8192;     // [d][j] 128x64
    float* Vs = sm + 16384;    // [j][c] 64x128
    float* Ps = sm + 24576;    // [j][i] 64x64  (P transposed)

    const int qt = (int)gridDim.x - 1 - (int)blockIdx.x;   // heavy tiles first
    const int h  = blockIdx.y;
    const int b  = blockIdx.z;
    const int kvh = h >> 2;
    const int tid = threadIdx.x;
    const int tx = tid & 15, ty = tid >> 4;

    const float* Qg = qkv + ((size_t)(b * SLEN + qt * 64)) * QKVW + h * HDIM;
    const float* Kg = qkv + ((size_t)(b * SLEN)) * QKVW + 4096 + kvh * HDIM;
    const float* Vg = Kg + 1024;

    // Load Q tile (transposed into Qs[d][i])
    for (int idx = tid; idx < 64 * 32; idx += 256) {
        int i  = idx >> 5;
        int d4 = (idx & 31) << 2;
        float4 v = *(const float4*)(Qg + (size_t)i * QKVW + d4);
        Qs[(d4 + 0) * 64 + i] = v.x;
        Qs[(d4 + 1) * 64 + i] = v.y;
        Qs[(d4 + 2) * 64 + i] = v.z;
        Qs[(d4 + 3) * 64 + i] = v.w;
    }

    float m_i[4], l_i[4], o[4][8];
#pragma unroll
    for (int ii = 0; ii < 4; ii++) {
        m_i[ii] = -1e30f; l_i[ii] = 0.f;
#pragma unroll
        for (int cc = 0; cc < 8; cc++) o[ii][cc] = 0.f;
    }

    for (int kt = 0; kt <= qt; kt++) {
        __syncthreads();   // protect Ks/Vs/Ps reuse from previous iter
        for (int idx = tid; idx < 64 * 32; idx += 256) {
            int j  = idx >> 5;
            int d4 = (idx & 31) << 2;
            const float* kp = Kg + (size_t)(kt * 64 + j) * QKVW + d4;
            float4 kv4 = *(const float4*)kp;
            Ks[(d4 + 0) * 64 + j] = kv4.x;
            Ks[(d4 + 1) * 64 + j] = kv4.y;
            Ks[(d4 + 2) * 64 + j] = kv4.z;
            Ks[(d4 + 3) * 64 + j] = kv4.w;
            float4 vv4 = *(const float4*)(Vg + (size_t)(kt * 64 + j) * QKVW + d4);
            *(float4*)&Vs[j * 128 + d4] = vv4;
        }
        __syncthreads();

        float s[4][4];
#pragma unroll
        for (int ii = 0; ii < 4; ii++)
#pragma unroll
            for (int jj = 0; jj < 4; jj++) s[ii][jj] = 0.f;

#pragma unroll 8
        for (int d = 0; d < HDIM; d++) {
            float a[4], bb[4];
            *(float4*)a  = *(const float4*)&Qs[d * 64 + ty * 4];
            *(float4*)bb = *(const float4*)&Ks[d * 64 + tx * 4];
#pragma unroll
            for (int ii = 0; ii < 4; ii++)
#pragma unroll
                for (int jj = 0; jj < 4; jj++)
                    s[ii][jj] = fmaf(a[ii], bb[jj], s[ii][jj]);
        }

        const bool diag = (kt == qt);
        float rmax[4];
#pragma unroll
        for (int ii = 0; ii < 4; ii++) {
#pragma unroll
            for (int jj = 0; jj < 4; jj++) {
                float v = s[ii][jj] * ATT_SCALE;
                if (diag && (tx * 4 + jj) > (ty * 4 + ii)) v = -1e30f;
                s[ii][jj] = v;
            }
            rmax[ii] = fmaxf(fmaxf(s[ii][0], s[ii][1]), fmaxf(s[ii][2], s[ii][3]));
        }
#pragma unroll
        for (int off = 8; off >= 1; off >>= 1)
#pragma unroll
            for (int ii = 0; ii < 4; ii++)
                rmax[ii] = fmaxf(rmax[ii], __shfl_xor_sync(0xffffffffu, rmax[ii], off));

        float rsum[4];
#pragma unroll
        for (int ii = 0; ii < 4; ii++) {
            float mn = fmaxf(m_i[ii], rmax[ii]);
            float alpha = __expf(m_i[ii] - mn);
            m_i[ii] = mn;
            float rs = 0.f;
#pragma unroll
            for (int jj = 0; jj < 4; jj++) {
                float p = __expf(s[ii][jj] - mn);
                s[ii][jj] = p;
                rs += p;
            }
            rsum[ii] = rs;
            l_i[ii] *= alpha;
#pragma unroll
            for (int cc = 0; cc < 8; cc++) o[ii][cc] *= alpha;
        }
#pragma unroll
        for (int off = 8; off >= 1; off >>= 1)
#pragma unroll
            for (int ii = 0; ii < 4; ii++)
                rsum[ii] += __shfl_xor_sync(0xffffffffu, rsum[ii], off);
#pragma unroll
        for (int ii = 0; ii < 4; ii++) l_i[ii] += rsum[ii];

        // store P transposed: Ps[j][i]
#pragma unroll
        for (int ii = 0; ii < 4; ii++)
#pragma unroll
            for (int jj = 0; jj < 4; jj++)
                Ps[(tx * 4 + jj) * 64 + ty * 4 + ii] = s[ii][jj];
        __syncthreads();

#pragma unroll 4
        for (int j = 0; j < 64; j++) {
            float p4[4], v8[8];
            *(float4*)p4     = *(const float4*)&Ps[j * 64 + ty * 4];
            *(float4*)&v8[0] = *(const float4*)&Vs[j * 128 + tx * 8];
            *(float4*)&v8[4] = *(const float4*)&Vs[j * 128 + tx * 8 + 4];
#pragma unroll
            for (int ii = 0; ii < 4; ii++)
#pragma unroll
                for (int cc = 0; cc < 8; cc++)
                    o[ii][cc] = fmaf(p4[ii], v8[cc], o[ii][cc]);
        }
    }

    // epilogue: divide by l, write to g_att [tok][4096]
#pragma unroll
    for (int ii = 0; ii < 4; ii++) {
        float inv = 1.0f / l_i[ii];
        int q = qt * 64 + ty * 4 + ii;
        float* op = outp + ((size_t)(b * SLEN + q)) * DMODEL + h * HDIM + tx * 8;
        *(float4*)op       = make_float4(o[ii][0] * inv, o[ii][1] * inv, o[ii][2] * inv, o[ii][3] * inv);
        *(float4*)(op + 4) = make_float4(o[ii][4] * inv, o[ii][5] * inv, o[ii][6] * inv, o[ii][7] * inv);
    }
}

// ---------------------------------------------------------------------------
// Launch
// inputs: 0=x 1=mask(all-true, ignored) 2=cos 3=sin 4=wq 5=wk 6=wv 7=wo
// ---------------------------------------------------------------------------
extern "C" void kernel_launch(void* const* d_in, const int* in_sizes, int n_in,
                              void* d_out, int out_size)
{
    const float* x    = (const float*)d_in[0];
    const float* cosp = (const float*)d_in[2];
    const float* sinp = (const float*)d_in[3];
    const float* wq   = (const float*)d_in[4];
    const float* wk   = (const float*)d_in[5];
    const float* wv   = (const float*)d_in[6];
    const float* wo   = (const float*)d_in[7];
    float* outp = (float*)d_out;

    float *qkv, *att;
    cudaGetSymbolAddress((void**)&qkv, g_qkv);
    cudaGetSymbolAddress((void**)&att, g_att);

    const int FLASH_SMEM = 28672 * 4;  // 112 KB
    cudaFuncSetAttribute(flash_kernel, cudaFuncAttributeMaxDynamicSharedMemorySize, FLASH_SMEM);

    dim3 thr(256);
    // QKV projections into the fused [tok][6144] buffer
    sgemm_tn<<<dim3(32, 32), thr>>>(x, wq, qkv,        DMODEL, QKVW);
    sgemm_tn<<<dim3(8,  32), thr>>>(x, wk, qkv + 4096, DMODEL, QKVW);
    sgemm_tn<<<dim3(8,  32), thr>>>(x, wv, qkv + 5120, DMODEL, QKVW);
    // RoPE in place on q and k
    rope_kernel<<<(NTOK * 40 * 64) / 256, 256>>>(qkv, cosp, sinp);
    // Causal GQA attention
    flash_kernel<<<dim3(SLEN / 64, NHEAD, BATCH), thr, FLASH_SMEM>>>(qkv, att);
    // Output projection
    sgemm_tn<<<dim3(32, 32), thr>>>(att, wo, outp, DMODEL, DMODEL);
}

// round 5
// speedup vs baseline: 1.8163x; 1.8163x over previous
#include <cuda_runtime.h>
#include <cuda_bf16.h>
#include <cstdint>

// Problem constants
#define BATCH 2
#define SLEN  2048
#define DMODEL 4096
#define NHEAD 32
#define NKVH  8
#define HDIM  128
#define NTOK  (BATCH*SLEN)          // 4096
#define QKVW  6144                  // 4096 q + 1024 k + 1024 v
#define ATT_SCALE 0.08838834764831845f

// ---------------------------------------------------------------------------
// Scratch (allocation-free rule: __device__ globals)
// ---------------------------------------------------------------------------
__device__ float g_qkv[(size_t)NTOK * QKVW];     // q|k|v per token (fp32)
__device__ float g_att[(size_t)NTOK * DMODEL];   // attention output (fp32)
__device__ __nv_bfloat16 g_xhi[(size_t)NTOK * DMODEL];
__device__ __nv_bfloat16 g_xlo[(size_t)NTOK * DMODEL];
__device__ __nv_bfloat16 g_whi[(size_t)QKVW * DMODEL];   // fused wq|wk|wv rows
__device__ __nv_bfloat16 g_wlo[(size_t)QKVW * DMODEL];
__device__ __nv_bfloat16 g_wohi[(size_t)DMODEL * DMODEL];
__device__ __nv_bfloat16 g_wolo[(size_t)DMODEL * DMODEL];
__device__ __nv_bfloat16 g_ahi[(size_t)NTOK * DMODEL];
__device__ __nv_bfloat16 g_alo[(size_t)NTOK * DMODEL];

// ---------------------------------------------------------------------------
// Helpers
// ---------------------------------------------------------------------------
__device__ __forceinline__ uint32_t smem_u32(const void* p) {
    uint32_t a;
    asm("{ .reg .u64 t; cvta.to.shared.u64 t, %1; cvt.u32.u64 %0, t; }" : "=r"(a) : "l"(p));
    return a;
}
__device__ __forceinline__ void cp16(uint32_t dst, const void* src) {
    asm volatile("cp.async.cg.shared.global [%0], [%1], 16;" :: "r"(dst), "l"(src));
}
__device__ __forceinline__ void ldsm_x4(uint32_t* r, uint32_t addr) {
    asm volatile("ldmatrix.sync.aligned.m8n8.x4.shared.b16 {%0,%1,%2,%3}, [%4];"
                 : "=r"(r[0]), "=r"(r[1]), "=r"(r[2]), "=r"(r[3]) : "r"(addr));
}
__device__ __forceinline__ void ldsm_x2(uint32_t* r, uint32_t addr) {
    asm volatile("ldmatrix.sync.aligned.m8n8.x2.shared.b16 {%0,%1}, [%2];"
                 : "=r"(r[0]), "=r"(r[1]) : "r"(addr));
}
__device__ __forceinline__ void mma16816(float* d, const uint32_t* a, const uint32_t* b) {
    asm volatile("mma.sync.aligned.m16n8k16.row.col.f32.bf16.bf16.f32 "
                 "{%0,%1,%2,%3}, {%4,%5,%6,%7}, {%8,%9}, {%0,%1,%2,%3};"
                 : "+f"(d[0]), "+f"(d[1]), "+f"(d[2]), "+f"(d[3])
                 : "r"(a[0]), "r"(a[1]), "r"(a[2]), "r"(a[3]), "r"(b[0]), "r"(b[1]));
}

// ---------------------------------------------------------------------------
// bf16 split HGEMM via mma.sync (HMMA):
// C[M][N] = Ahi*Bhi^T + Ahi*Blo^T + Alo*Bhi^T  (A,B row-major, K contiguous)
// CTA 128x128, BK=32, 8 warps (warp tile 64x32), 3-stage cp.async pipeline.
// grid: (M/128, N/128), 256 threads.
// ---------------------------------------------------------------------------
#define ROWB   80                    // 64 data bytes + 16 pad per smem row
#define BUFB   (128 * ROWB)          // one operand buffer (128 rows)
#define STAGEB (4 * BUFB)            // Ahi | Alo | Bhi | Blo
#define NSTAGE 3
#define GSMEM  (NSTAGE * STAGEB)     // 122880 B

__global__ __launch_bounds__(256, 1) void gemm_mma_split(
    const __nv_bfloat16* __restrict__ Ahi, const __nv_bfloat16* __restrict__ Alo,
    const __nv_bfloat16* __restrict__ Bhi, const __nv_bfloat16* __restrict__ Blo,
    float* __restrict__ C, int K, int ldc)
{
    extern __shared__ char dynsm[];
    const uint32_t smb = smem_u32(dynsm);
    const int tid  = threadIdx.x;
    const int wid  = tid >> 5;
    const int lane = tid & 31;
    const int m0 = blockIdx.x * 128;
    const int n0 = blockIdx.y * 128;
    const int nch = K >> 5;

    const __nv_bfloat16* srcs[4] = { Ahi, Alo, Bhi, Blo };
    const int bases[4] = { m0, m0, n0, n0 };

    auto load_stage = [&](int c, int st) {
        const uint32_t sb = smb + st * STAGEB;
#pragma unroll
        for (int buf = 0; buf < 4; buf++) {
            const __nv_bfloat16* src = srcs[buf] + (size_t)bases[buf] * K + c * 32;
#pragma unroll
            for (int i = 0; i < 2; i++) {
                int o = i * 256 + tid;
                int r = o >> 2, s = o & 3;
                cp16(sb + buf * BUFB + r * ROWB + s * 16,
                     src + (size_t)r * K + s * 8);
            }
        }
        asm volatile("cp.async.commit_group;" ::: "memory");
    };

    float acc[4][4][4];
#pragma unroll
    for (int mt = 0; mt < 4; mt++)
#pragma unroll
        for (int nt = 0; nt < 4; nt++)
#pragma unroll
            for (int q = 0; q < 4; q++) acc[mt][nt][q] = 0.f;

    load_stage(0, 0);
    load_stage(1, 1);

    const int wm = (wid >> 2) * 64;            // warp m offset in tile
    const int wn = (wid & 3) * 32;             // warp n offset
    const int arow = lane & 15, acolg = lane >> 4;
    const int brow = lane & 7,  bcolg = (lane >> 3) & 1;

    for (int c = 0; c < nch; c++) {
        // RAW: pending groups here are exactly {c, c+1}; wait_group 1 -> stage c done.
        if (c + 1 < nch) asm volatile("cp.async.wait_group 1;" ::: "memory");
        else             asm volatile("cp.async.wait_group 0;" ::: "memory");
        __syncthreads();
        // WAR-safe: buffer (c+2)%3 == (c-1)%3 was last read in compute c-1,
        // which precedes this barrier in every thread's program order.
        if (c + 2 < nch) load_stage(c + 2, (c + 2) % NSTAGE);

        const uint32_t sb   = smb + (c % NSTAGE) * STAGEB;
        const uint32_t aHiB = sb;
        const uint32_t aLoB = sb + BUFB;
        const uint32_t bHiB = sb + 2 * BUFB;
        const uint32_t bLoB = sb + 3 * BUFB;

#pragma unroll
        for (int ks = 0; ks < 2; ks++) {
            const int kb = ks * 32;   // byte offset of k16 step
            uint32_t ah[4][4], al[4][4], bh[4][2], bl[4][2];
#pragma unroll
            for (int mt = 0; mt < 4; mt++) {
                uint32_t ao = (wm + mt * 16 + arow) * ROWB + kb + acolg * 16;
                ldsm_x4(ah[mt], aHiB + ao);
                ldsm_x4(al[mt], aLoB + ao);
            }
#pragma unroll
            for (int nt = 0; nt < 4; nt++) {
                uint32_t bo = (wn + nt * 8 + brow) * ROWB + kb + bcolg * 16;
                ldsm_x2(bh[nt], bHiB + bo);
                ldsm_x2(bl[nt], bLoB + bo);
            }
#pragma unroll
            for (int mt = 0; mt < 4; mt++)
#pragma unroll
                for (int nt = 0; nt < 4; nt++) {
                    mma16816(acc[mt][nt], ah[mt], bh[nt]);
                    mma16816(acc[mt][nt], ah[mt], bl[nt]);
                    mma16816(acc[mt][nt], al[mt], bh[nt]);
                }
        }
    }

    // Epilogue: write fp32 C
#pragma unroll
    for (int mt = 0; mt < 4; mt++) {
        int r0 = m0 + wm + mt * 16 + (lane >> 2);
#pragma unroll
        for (int nt = 0; nt < 4; nt++) {
            int cc = n0 + wn + nt * 8 + (lane & 3) * 2;
            *(float2*)(C + (size_t)r0 * ldc + cc)       = make_float2(acc[mt][nt][0], acc[mt][nt][1]);
            *(float2*)(C + (size_t)(r0 + 8) * ldc + cc) = make_float2(acc[mt][nt][2], acc[mt][nt][3]);
        }
    }
}

// ---------------------------------------------------------------------------
// fp32 -> bf16 hi/lo split (4 elems/thread)
// ---------------------------------------------------------------------------
__global__ void split_bf16(const float* __restrict__ src,
                           __nv_bfloat16* __restrict__ hi,
                           __nv_bfloat16* __restrict__ lo, int n)
{
    int i = (blockIdx.x * 256 + threadIdx.x) * 4;
    if (i >= n) return;
    float4 v = *(const float4*)(src + i);
    __nv_bfloat16 h0 = __float2bfloat16(v.x), h1 = __float2bfloat16(v.y);
    __nv_bfloat16 h2 = __float2bfloat16(v.z), h3 = __float2bfloat16(v.w);
    __nv_bfloat16 l0 = __float2bfloat16(v.x - __bfloat162float(h0));
    __nv_bfloat16 l1 = __float2bfloat16(v.y - __bfloat162float(h1));
    __nv_bfloat16 l2 = __float2bfloat16(v.z - __bfloat162float(h2));
    __nv_bfloat16 l3 = __float2bfloat16(v.w - __bfloat162float(h3));
    __nv_bfloat162 hp[2] = {{h0, h1}, {h2, h3}};
    __nv_bfloat162 lp[2] = {{l0, l1}, {l2, l3}};
    *(uint2*)(hi + i) = *(uint2*)hp;
    *(uint2*)(lo + i) = *(uint2*)lp;
}

// ---------------------------------------------------------------------------
// RoPE (interleaved pairs), in place on q + k of g_qkv
// ---------------------------------------------------------------------------
__global__ void rope_kernel(float* __restrict__ qkv,
                            const float* __restrict__ cosp,
                            const float* __restrict__ sinp)
{
    int idx = blockIdx.x * 256 + threadIdx.x;
    if (idx >= NTOK * 40 * 64) return;
    int p  = idx & 63;
    int h2 = (idx >> 6) % 40;
    int t  = idx / (64 * 40);
    float c  = cosp[(size_t)t * 64 + p];
    float sn = sinp[(size_t)t * 64 + p];
    size_t base = (size_t)t * QKVW + (h2 < 32 ? h2 * HDIM : 4096 + (h2 - 32) * HDIM) + 2 * p;
    float t0 = qkv[base], t1 = qkv[base + 1];
    qkv[base]     = t0 * c - t1 * sn;
    qkv[base + 1] = t0 * sn + t1 * c;
}

// ---------------------------------------------------------------------------
// Flash attention (fp32, causal, GQA 4:1) — unchanged (known correct)
// ---------------------------------------------------------------------------
__global__ __launch_bounds__(256) void flash_kernel(const float* __restrict__ qkv,
                                                    float* __restrict__ outp)
{
    extern __shared__ float sm[];
    float* Qs = sm;            // [d][i] 128x64
    float* Ks = sm + 8192;     // [d][j] 128x64
    float* Vs = sm + 16384;    // [j][c] 64x128
    float* Ps = sm + 24576;    // [j][i] 64x64

    const int qt = (int)gridDim.x - 1 - (int)blockIdx.x;
    const int h  = blockIdx.y;
    const int b  = blockIdx.z;
    const int kvh = h >> 2;
    const int tid = threadIdx.x;
    const int tx = tid & 15, ty = tid >> 4;

    const float* Qg = qkv + ((size_t)(b * SLEN + qt * 64)) * QKVW + h * HDIM;
    const float* Kg = qkv + ((size_t)(b * SLEN)) * QKVW + 4096 + kvh * HDIM;
    const float* Vg = Kg + 1024;

    for (int idx = tid; idx < 64 * 32; idx += 256) {
        int i  = idx >> 5;
        int d4 = (idx & 31) << 2;
        float4 v = *(const float4*)(Qg + (size_t)i * QKVW + d4);
        Qs[(d4 + 0) * 64 + i] = v.x;
        Qs[(d4 + 1) * 64 + i] = v.y;
        Qs[(d4 + 2) * 64 + i] = v.z;
        Qs[(d4 + 3) * 64 + i] = v.w;
    }

    float m_i[4], l_i[4], o[4][8];
#pragma unroll
    for (int ii = 0; ii < 4; ii++) {
        m_i[ii] = -1e30f; l_i[ii] = 0.f;
#pragma unroll
        for (int cc = 0; cc < 8; cc++) o[ii][cc] = 0.f;
    }

    for (int kt = 0; kt <= qt; kt++) {
        __syncthreads();
        for (int idx = tid; idx < 64 * 32; idx += 256) {
            int j  = idx >> 5;
            int d4 = (idx & 31) << 2;
            const float* kp = Kg + (size_t)(kt * 64 + j) * QKVW + d4;
            float4 kv4 = *(const float4*)kp;
            Ks[(d4 + 0) * 64 + j] = kv4.x;
            Ks[(d4 + 1) * 64 + j] = kv4.y;
            Ks[(d4 + 2) * 64 + j] = kv4.z;
            Ks[(d4 + 3) * 64 + j] = kv4.w;
            float4 vv4 = *(const float4*)(Vg + (size_t)(kt * 64 + j) * QKVW + d4);
            *(float4*)&Vs[j * 128 + d4] = vv4;
        }
        __syncthreads();

        float s[4][4];
#pragma unroll
        for (int ii = 0; ii < 4; ii++)
#pragma unroll
            for (int jj = 0; jj < 4; jj++) s[ii][jj] = 0.f;

#pragma unroll 8
        for (int d = 0; d < HDIM; d++) {
            float a[4], bb[4];
            *(float4*)a  = *(const float4*)&Qs[d * 64 + ty * 4];
            *(float4*)bb = *(const float4*)&Ks[d * 64 + tx * 4];
#pragma unroll
            for (int ii = 0; ii < 4; ii++)
#pragma unroll
                for (int jj = 0; jj < 4; jj++)
                    s[ii][jj] = fmaf(a[ii], bb[jj], s[ii][jj]);
        }

        const bool diag = (kt == qt);
        float rmax[4];
#pragma unroll
        for (int ii = 0; ii < 4; ii++) {
#pragma unroll
            for (int jj = 0; jj < 4; jj++) {
                float v = s[ii][jj] * ATT_SCALE;
                if (diag && (tx * 4 + jj) > (ty * 4 + ii)) v = -1e30f;
                s[ii][jj] = v;
            }
            rmax[ii] = fmaxf(fmaxf(s[ii][0], s[ii][1]), fmaxf(s[ii][2], s[ii][3]));
        }
#pragma unroll
        for (int off = 8; off >= 1; off >>= 1)
#pragma unroll
            for (int ii = 0; ii < 4; ii++)
                rmax[ii] = fmaxf(rmax[ii], __shfl_xor_sync(0xffffffffu, rmax[ii], off));

        float rsum[4];
#pragma unroll
        for (int ii = 0; ii < 4; ii++) {
            float mn = fmaxf(m_i[ii], rmax[ii]);
            float alpha = __expf(m_i[ii] - mn);
            m_i[ii] = mn;
            float rs = 0.f;
#pragma unroll
            for (int jj = 0; jj < 4; jj++) {
                float p = __expf(s[ii][jj] - mn);
                s[ii][jj] = p;
                rs += p;
            }
            rsum[ii] = rs;
            l_i[ii] *= alpha;
#pragma unroll
            for (int cc = 0; cc < 8; cc++) o[ii][cc] *= alpha;
        }
#pragma unroll
        for (int off = 8; off >= 1; off >>= 1)
#pragma unroll
            for (int ii = 0; ii < 4; ii++)
                rsum[ii] += __shfl_xor_sync(0xffffffffu, rsum[ii], off);
#pragma unroll
        for (int ii = 0; ii < 4; ii++) l_i[ii] += rsum[ii];

#pragma unroll
        for (int ii = 0; ii < 4; ii++)
#pragma unroll
            for (int jj = 0; jj < 4; jj++)
                Ps[(tx * 4 + jj) * 64 + ty * 4 + ii] = s[ii][jj];
        __syncthreads();

#pragma unroll 4
        for (int j = 0; j < 64; j++) {
            float p4[4], v8[8];
            *(float4*)p4     = *(const float4*)&Ps[j * 64 + ty * 4];
            *(float4*)&v8[0] = *(const float4*)&Vs[j * 128 + tx * 8];
            *(float4*)&v8[4] = *(const float4*)&Vs[j * 128 + tx * 8 + 4];
#pragma unroll
            for (int ii = 0; ii < 4; ii++)
#pragma unroll
                for (int cc = 0; cc < 8; cc++)
                    o[ii][cc] = fmaf(p4[ii], v8[cc], o[ii][cc]);
        }
    }

#pragma unroll
    for (int ii = 0; ii < 4; ii++) {
        float inv = 1.0f / l_i[ii];
        int q = qt * 64 + ty * 4 + ii;
        float* op = outp + ((size_t)(b * SLEN + q)) * DMODEL + h * HDIM + tx * 8;
        *(float4*)op       = make_float4(o[ii][0] * inv, o[ii][1] * inv, o[ii][2] * inv, o[ii][3] * inv);
        *(float4*)(op + 4) = make_float4(o[ii][4] * inv, o[ii][5] * inv, o[ii][6] * inv, o[ii][7] * inv);
    }
}

// ---------------------------------------------------------------------------
// Launch. inputs: 0=x 1=mask(all-true) 2=cos 3=sin 4=wq 5=wk 6=wv 7=wo
// ---------------------------------------------------------------------------
extern "C" void kernel_launch(void* const* d_in, const int* in_sizes, int n_in,
                              void* d_out, int out_size)
{
    const float* x    = (const float*)d_in[0];
    const float* cosp = (const float*)d_in[2];
    const float* sinp = (const float*)d_in[3];
    const float* wq   = (const float*)d_in[4];
    const float* wk   = (const float*)d_in[5];
    const float* wv   = (const float*)d_in[6];
    const float* wo   = (const float*)d_in[7];
    float* outp = (float*)d_out;

    float *qkv, *att;
    __nv_bfloat16 *xhi, *xlo, *whi, *wlo, *wohi, *wolo, *ahi, *alo;
    cudaGetSymbolAddress((void**)&qkv,  g_qkv);
    cudaGetSymbolAddress((void**)&att,  g_att);
    cudaGetSymbolAddress((void**)&xhi,  g_xhi);
    cudaGetSymbolAddress((void**)&xlo,  g_xlo);
    cudaGetSymbolAddress((void**)&whi,  g_whi);
    cudaGetSymbolAddress((void**)&wlo,  g_wlo);
    cudaGetSymbolAddress((void**)&wohi, g_wohi);
    cudaGetSymbolAddress((void**)&wolo, g_wolo);
    cudaGetSymbolAddress((void**)&ahi,  g_ahi);
    cudaGetSymbolAddress((void**)&alo,  g_alo);

    const int FLASH_SMEM = 28672 * 4;  // 112 KB
    cudaFuncSetAttribute(flash_kernel, cudaFuncAttributeMaxDynamicSharedMemorySize, FLASH_SMEM);
    cudaFuncSetAttribute(gemm_mma_split, cudaFuncAttributeMaxDynamicSharedMemorySize, GSMEM);

    // bf16 hi/lo splits (weights fused into one [6144][4096] buffer)
    const int NX = NTOK * DMODEL;            // 16.7M
    const int NW = DMODEL * DMODEL;          // 16.7M
    const int NK = NKVH * HDIM * DMODEL;     // 4.2M
    split_bf16<<<NX / 1024, 256>>>(x,  xhi,  xlo,  NX);
    split_bf16<<<NW / 1024, 256>>>(wq, whi,  wlo,  NW);
    split_bf16<<<NK / 1024, 256>>>(wk, whi + (size_t)4096 * DMODEL, wlo + (size_t)4096 * DMODEL, NK);
    split_bf16<<<NK / 1024, 256>>>(wv, whi + (size_t)5120 * DMODEL, wlo + (size_t)5120 * DMODEL, NK);
    split_bf16<<<NW / 1024, 256>>>(wo, wohi, wolo, NW);

    // Fused QKV projection: [4096 tok] x [6144 rows] over K=4096
    gemm_mma_split<<<dim3(NTOK / 128, QKVW / 128), 256, GSMEM>>>(
        xhi, xlo, whi, wlo, qkv, DMODEL, QKVW);

    // RoPE in place on q and k
    rope_kernel<<<(NTOK * 40 * 64) / 256, 256>>>(qkv, cosp, sinp);

    // Causal GQA attention (fp32)
    flash_kernel<<<dim3(SLEN / 64, NHEAD, BATCH), 256, FLASH_SMEM>>>(qkv, att);

    // Output projection
    split_bf16<<<NX / 1024, 256>>>(att, ahi, alo, NX);
    gemm_mma_split<<<dim3(NTOK / 128, DMODEL / 128), 256, GSMEM>>>(
        ahi, alo, wohi, wolo, outp, DMODEL, DMODEL);
}

// round 6
// speedup vs baseline: 3.0419x; 1.6748x over previous
#include <cuda_runtime.h>
#include <cuda_bf16.h>
#include <cstdint>

// Problem constants
#define BATCH 2
#define SLEN  2048
#define DMODEL 4096
#define NHEAD 32
#define NKVH  8
#define HDIM  128
#define NTOK  (BATCH*SLEN)          // 4096
#define QKVW  6144                  // 4096 q + 1024 k + 1024 v
#define ATT_SCALE 0.08838834764831845f

// ---------------------------------------------------------------------------
// Scratch (allocation-free rule: __device__ globals)
// ---------------------------------------------------------------------------
__device__ __nv_bfloat16 g_xhi[(size_t)NTOK * DMODEL];
__device__ __nv_bfloat16 g_xlo[(size_t)NTOK * DMODEL];
__device__ __nv_bfloat16 g_whi[(size_t)QKVW * DMODEL];   // fused wq|wk|wv rows
__device__ __nv_bfloat16 g_wlo[(size_t)QKVW * DMODEL];
__device__ __nv_bfloat16 g_wohi[(size_t)DMODEL * DMODEL];
__device__ __nv_bfloat16 g_wolo[(size_t)DMODEL * DMODEL];
__device__ __nv_bfloat16 g_qkvhi[(size_t)NTOK * QKVW];
__device__ __nv_bfloat16 g_qkvlo[(size_t)NTOK * QKVW];
__device__ __nv_bfloat16 g_ahi[(size_t)NTOK * DMODEL];
__device__ __nv_bfloat16 g_alo[(size_t)NTOK * DMODEL];

// ---------------------------------------------------------------------------
// Helpers
// ---------------------------------------------------------------------------
__device__ __forceinline__ uint32_t smem_u32(const void* p) {
    uint32_t a;
    asm("{ .reg .u64 t; cvta.to.shared.u64 t, %1; cvt.u32.u64 %0, t; }" : "=r"(a) : "l"(p));
    return a;
}
__device__ __forceinline__ void cp16(uint32_t dst, const void* src) {
    asm volatile("cp.async.cg.shared.global [%0], [%1], 16;" :: "r"(dst), "l"(src));
}
__device__ __forceinline__ void ldsm_x4(uint32_t* r, uint32_t addr) {
    asm volatile("ldmatrix.sync.aligned.m8n8.x4.shared.b16 {%0,%1,%2,%3}, [%4];"
                 : "=r"(r[0]), "=r"(r[1]), "=r"(r[2]), "=r"(r[3]) : "r"(addr));
}
__device__ __forceinline__ void ldsm_x4t(uint32_t* r, uint32_t addr) {
    asm volatile("ldmatrix.sync.aligned.m8n8.x4.trans.shared.b16 {%0,%1,%2,%3}, [%4];"
                 : "=r"(r[0]), "=r"(r[1]), "=r"(r[2]), "=r"(r[3]) : "r"(addr));
}
__device__ __forceinline__ void ldsm_x2(uint32_t* r, uint32_t addr) {
    asm volatile("ldmatrix.sync.aligned.m8n8.x2.shared.b16 {%0,%1}, [%2];"
                 : "=r"(r[0]), "=r"(r[1]) : "r"(addr));
}
__device__ __forceinline__ void mma16816(float* d, const uint32_t* a, const uint32_t* b) {
    asm volatile("mma.sync.aligned.m16n8k16.row.col.f32.bf16.bf16.f32 "
                 "{%0,%1,%2,%3}, {%4,%5,%6,%7}, {%8,%9}, {%0,%1,%2,%3};"
                 : "+f"(d[0]), "+f"(d[1]), "+f"(d[2]), "+f"(d[3])
                 : "r"(a[0]), "r"(a[1]), "r"(a[2]), "r"(a[3]), "r"(b[0]), "r"(b[1]));
}
// split fp32 pair -> (hi u32 bf16x2, lo u32 bf16x2)
__device__ __forceinline__ uint32_t pack_hl(float f0, float f1, uint32_t& lo) {
    __nv_bfloat16 h0 = __float2bfloat16(f0), h1 = __float2bfloat16(f1);
    __nv_bfloat16 l0 = __float2bfloat16(f0 - __bfloat162float(h0));
    __nv_bfloat16 l1 = __float2bfloat16(f1 - __bfloat162float(h1));
    __nv_bfloat162 hp(h0, h1), lp(l0, l1);
    lo = *(uint32_t*)&lp;
    return *(uint32_t*)&hp;
}
__device__ __forceinline__ uint32_t pack2(float f0, float f1) {
    __nv_bfloat162 hp(__float2bfloat16(f0), __float2bfloat16(f1));
    return *(uint32_t*)&hp;
}

// ---------------------------------------------------------------------------
// bf16 split HGEMM via mma.sync:
// C = Ahi*Bhi^T + Ahi*Blo^T + Alo*Bhi^T.  Epilogue: fp32 C, or hi/lo split.
// CTA 128x128, BK=32, 8 warps (warp tile 64x32), 3-stage cp.async pipeline.
// ---------------------------------------------------------------------------
#define ROWB   80
#define BUFB   (128 * ROWB)
#define STAGEB (4 * BUFB)
#define NSTAGE 3
#define GSMEM  (NSTAGE * STAGEB)     // 122880 B

__global__ __launch_bounds__(256, 1) void gemm_mma_split(
    const __nv_bfloat16* __restrict__ Ahi, const __nv_bfloat16* __restrict__ Alo,
    const __nv_bfloat16* __restrict__ Bhi, const __nv_bfloat16* __restrict__ Blo,
    float* __restrict__ C, __nv_bfloat16* __restrict__ Chi, __nv_bfloat16* __restrict__ Clo,
    int K, int ldc)
{
    extern __shared__ char dynsm[];
    const uint32_t smb = smem_u32(dynsm);
    const int tid  = threadIdx.x;
    const int wid  = tid >> 5;
    const int lane = tid & 31;
    const int m0 = blockIdx.x * 128;
    const int n0 = blockIdx.y * 128;
    const int nch = K >> 5;

    const __nv_bfloat16* srcs[4] = { Ahi, Alo, Bhi, Blo };
    const int bases[4] = { m0, m0, n0, n0 };

    auto load_stage = [&](int c, int st) {
        const uint32_t sb = smb + st * STAGEB;
#pragma unroll
        for (int buf = 0; buf < 4; buf++) {
            const __nv_bfloat16* src = srcs[buf] + (size_t)bases[buf] * K + c * 32;
#pragma unroll
            for (int i = 0; i < 2; i++) {
                int o = i * 256 + tid;
                int r = o >> 2, s = o & 3;
                cp16(sb + buf * BUFB + r * ROWB + s * 16,
                     src + (size_t)r * K + s * 8);
            }
        }
        asm volatile("cp.async.commit_group;" ::: "memory");
    };

    float acc[4][4][4];
#pragma unroll
    for (int mt = 0; mt < 4; mt++)
#pragma unroll
        for (int nt = 0; nt < 4; nt++)
#pragma unroll
            for (int q = 0; q < 4; q++) acc[mt][nt][q] = 0.f;

    load_stage(0, 0);
    load_stage(1, 1);

    const int wm = (wid >> 2) * 64;
    const int wn = (wid & 3) * 32;
    const int arow = lane & 15, acolg = lane >> 4;
    const int brow = lane & 7,  bcolg = (lane >> 3) & 1;

    for (int c = 0; c < nch; c++) {
        if (c + 1 < nch) asm volatile("cp.async.wait_group 1;" ::: "memory");
        else             asm volatile("cp.async.wait_group 0;" ::: "memory");
        __syncthreads();
        if (c + 2 < nch) load_stage(c + 2, (c + 2) % NSTAGE);

        const uint32_t sb   = smb + (c % NSTAGE) * STAGEB;
        const uint32_t aHiB = sb;
        const uint32_t aLoB = sb + BUFB;
        const uint32_t bHiB = sb + 2 * BUFB;
        const uint32_t bLoB = sb + 3 * BUFB;

#pragma unroll
        for (int ks = 0; ks < 2; ks++) {
            const int kb = ks * 32;
            uint32_t ah[4][4], al[4][4], bh[4][2], bl[4][2];
#pragma unroll
            for (int mt = 0; mt < 4; mt++) {
                uint32_t ao = (wm + mt * 16 + arow) * ROWB + kb + acolg * 16;
                ldsm_x4(ah[mt], aHiB + ao);
                ldsm_x4(al[mt], aLoB + ao);
            }
#pragma unroll
            for (int nt = 0; nt < 4; nt++) {
                uint32_t bo = (wn + nt * 8 + brow) * ROWB + kb + bcolg * 16;
                ldsm_x2(bh[nt], bHiB + bo);
                ldsm_x2(bl[nt], bLoB + bo);
            }
#pragma unroll
            for (int mt = 0; mt < 4; mt++)
#pragma unroll
                for (int nt = 0; nt < 4; nt++) {
                    mma16816(acc[mt][nt], ah[mt], bh[nt]);
                    mma16816(acc[mt][nt], ah[mt], bl[nt]);
                    mma16816(acc[mt][nt], al[mt], bh[nt]);
                }
        }
    }

#pragma unroll
    for (int mt = 0; mt < 4; mt++) {
        int r0 = m0 + wm + mt * 16 + (lane >> 2);
#pragma unroll
        for (int nt = 0; nt < 4; nt++) {
            int cc = n0 + wn + nt * 8 + (lane & 3) * 2;
            if (Chi) {
                uint32_t lo0, lo1;
                uint32_t hi0 = pack_hl(acc[mt][nt][0], acc[mt][nt][1], lo0);
                uint32_t hi1 = pack_hl(acc[mt][nt][2], acc[mt][nt][3], lo1);
                *(uint32_t*)(Chi + (size_t)r0 * ldc + cc)       = hi0;
                *(uint32_t*)(Clo + (size_t)r0 * ldc + cc)       = lo0;
                *(uint32_t*)(Chi + (size_t)(r0 + 8) * ldc + cc) = hi1;
                *(uint32_t*)(Clo + (size_t)(r0 + 8) * ldc + cc) = lo1;
            } else {
                *(float2*)(C + (size_t)r0 * ldc + cc)       = make_float2(acc[mt][nt][0], acc[mt][nt][1]);
                *(float2*)(C + (size_t)(r0 + 8) * ldc + cc) = make_float2(acc[mt][nt][2], acc[mt][nt][3]);
            }
        }
    }
}

// ---------------------------------------------------------------------------
// fp32 -> bf16 hi/lo split (4 elems/thread)
// ---------------------------------------------------------------------------
__global__ void split_bf16(const float* __restrict__ src,
                           __nv_bfloat16* __restrict__ hi,
                           __nv_bfloat16* __restrict__ lo, int n)
{
    int i = (blockIdx.x * 256 + threadIdx.x) * 4;
    if (i >= n) return;
    float4 v = *(const float4*)(src + i);
    uint32_t l0, l1;
    uint32_t h0 = pack_hl(v.x, v.y, l0);
    uint32_t h1 = pack_hl(v.z, v.w, l1);
    *(uint2*)(hi + i) = make_uint2(h0, h1);
    *(uint2*)(lo + i) = make_uint2(l0, l1);
}

// ---------------------------------------------------------------------------
// RoPE on hi/lo representation, in place on q + k of g_qkvhi/g_qkvlo
// ---------------------------------------------------------------------------
__global__ void rope_hl(__nv_bfloat16* __restrict__ hi, __nv_bfloat16* __restrict__ lo,
                        const float* __restrict__ cosp, const float* __restrict__ sinp)
{
    int idx = blockIdx.x * 256 + threadIdx.x;
    if (idx >= NTOK * 40 * 64) return;
    int p  = idx & 63;
    int h2 = (idx >> 6) % 40;
    int t  = idx / (64 * 40);
    float c  = cosp[(size_t)t * 64 + p];
    float sn = sinp[(size_t)t * 64 + p];
    size_t base = (size_t)t * QKVW + (h2 < 32 ? h2 * HDIM : 4096 + (h2 - 32) * HDIM) + 2 * p;
    float t0 = __bfloat162float(hi[base])     + __bfloat162float(lo[base]);
    float t1 = __bfloat162float(hi[base + 1]) + __bfloat162float(lo[base + 1]);
    float r0 = t0 * c - t1 * sn;
    float r1 = t0 * sn + t1 * c;
    uint32_t lp;
    uint32_t hp = pack_hl(r0, r1, lp);
    *(uint32_t*)(hi + base) = hp;
    *(uint32_t*)(lo + base) = lp;
}

// ---------------------------------------------------------------------------
// Flash attention, tensor-core (bf16 3-term split), causal, GQA 4:1.
// CTA: 128 queries x (head, batch). 8 warps, each owns 16 query rows.
// KV tile 64, double-buffered cp.async. Output written as hi/lo bf16 split.
// ---------------------------------------------------------------------------
#define FROW    272                   // 128 bf16 = 256B + 16 pad
#define FQLO    (128 * FROW)          // 34816
#define FSTAGE0 (2 * 128 * FROW)      // 69632
#define FSTAGESZ (4 * 64 * FROW)      // 69632 : Khi|Klo|Vhi|Vlo
#define FK_HI 0
#define FK_LO (64 * FROW)
#define FV_HI (2 * 64 * FROW)
#define FV_LO (3 * 64 * FROW)
#define FSMEM (FSTAGE0 + 2 * FSTAGESZ)   // 208896 B

__global__ __launch_bounds__(256, 1) void flash_mma(
    const __nv_bfloat16* __restrict__ qhi, const __nv_bfloat16* __restrict__ qlo,
    __nv_bfloat16* __restrict__ ohi_g, __nv_bfloat16* __restrict__ olo_g)
{
    extern __shared__ char fsm[];
    const uint32_t smb = smem_u32(fsm);
    const int qt = 15 - (int)blockIdx.x;     // heavy tiles first
    const int h  = blockIdx.y;
    const int b  = blockIdx.z;
    const int kvh = h >> 2;
    const int tid = threadIdx.x, wid = tid >> 5, lane = tid & 31;
    const int nkt = 2 * qt + 2;

    const size_t tokQ = (size_t)b * SLEN + (size_t)qt * 128;
    const __nv_bfloat16* Qhg = qhi + tokQ * QKVW + h * HDIM;
    const __nv_bfloat16* Qlg = qlo + tokQ * QKVW + h * HDIM;
    const size_t kvbase = (size_t)b * SLEN * QKVW + kvh * HDIM;
    const __nv_bfloat16* Khg = qhi + kvbase + 4096;
    const __nv_bfloat16* Klg = qlo + kvbase + 4096;
    const __nv_bfloat16* Vhg = qhi + kvbase + 5120;
    const __nv_bfloat16* Vlg = qlo + kvbase + 5120;

    auto load_kv = [&](int kt, int buf) {
        const uint32_t sb = smb + FSTAGE0 + buf * FSTAGESZ;
#pragma unroll
        for (int i = 0; i < 4; i++) {
            int ch = tid + i * 256;
            int r = ch >> 4, s = ch & 15;
            size_t go = (size_t)(kt * 64 + r) * QKVW + s * 8;
            uint32_t so = r * FROW + s * 16;
            cp16(sb + FK_HI + so, Khg + go);
            cp16(sb + FK_LO + so, Klg + go);
            cp16(sb + FV_HI + so, Vhg + go);
            cp16(sb + FV_LO + so, Vlg + go);
        }
        asm volatile("cp.async.commit_group;" ::: "memory");
    };

    // Q load (joins KV(0)'s commit group)
#pragma unroll
    for (int i = 0; i < 8; i++) {
        int ch = tid + i * 256;
        int r = ch >> 4, s = ch & 15;
        size_t go = (size_t)r * QKVW + s * 8;
        uint32_t so = r * FROW + s * 16;
        cp16(smb + so,        Qhg + go);
        cp16(smb + FQLO + so, Qlg + go);
    }
    load_kv(0, 0);
    load_kv(1, 1);

    float o[16][4];
#pragma unroll
    for (int ct = 0; ct < 16; ct++)
#pragma unroll
        for (int q = 0; q < 4; q++) o[ct][q] = 0.f;
    float m0 = -1e30f, m1 = -1e30f, l0 = 0.f, l1 = 0.f;

    // fragment address components
    const uint32_t aAddr0 = smb + (wid * 16 + (lane & 15)) * FROW + (lane >> 4) * 16;
    const int brow = ((lane >> 4) << 3) + (lane & 7);     // K: row within 16-row pair
    const int bkof = ((lane >> 3) & 1) * 16;              // K: k-half byte offset
    const int vrowl = ((lane >> 3) & 1) * 8 + (lane & 7); // V: row within 16-j group
    const int vcof = ((lane >> 4) << 3) * 2;              // V: ct-half byte offset

    for (int kt = 0; kt < nkt; kt++) {
        if (kt + 1 < nkt) asm volatile("cp.async.wait_group 1;" ::: "memory");
        else              asm volatile("cp.async.wait_group 0;" ::: "memory");
        __syncthreads();

        const uint32_t Kb = smb + FSTAGE0 + (kt & 1) * FSTAGESZ;

        // ---- S = Q K^T (3 split terms), 64 cols ----
        float s[8][4];
#pragma unroll
        for (int nt = 0; nt < 8; nt++)
#pragma unroll
            for (int q = 0; q < 4; q++) s[nt][q] = 0.f;

#pragma unroll
        for (int ks = 0; ks < 8; ks++) {
            uint32_t ah[4], al[4];
            ldsm_x4(ah, aAddr0 + ks * 32);
            ldsm_x4(al, aAddr0 + FQLO + ks * 32);
#pragma unroll
            for (int np = 0; np < 4; np++) {
                uint32_t bh[4], bl[4];
                uint32_t ba = Kb + (np * 16 + brow) * FROW + ks * 32 + bkof;
                ldsm_x4(bh, ba + FK_HI);
                ldsm_x4(bl, ba + FK_LO);
                mma16816(s[2 * np],     ah, bh);
                mma16816(s[2 * np],     ah, bl);
                mma16816(s[2 * np],     al, bh);
                mma16816(s[2 * np + 1], ah, bh + 2);
                mma16816(s[2 * np + 1], ah, bl + 2);
                mma16816(s[2 * np + 1], al, bh + 2);
            }
        }

        // ---- softmax (rows warp-local; reduce over lane&3) ----
        const bool need_mask = (kt >= 2 * qt);
        const int rg0 = qt * 128 + wid * 16 + (lane >> 2);
#pragma unroll
        for (int nt = 0; nt < 8; nt++) {
#pragma unroll
            for (int q = 0; q < 4; q++) {
                float v = s[nt][q] * ATT_SCALE;
                if (need_mask) {
                    int col = kt * 64 + nt * 8 + (lane & 3) * 2 + (q & 1);
                    int row = rg0 + ((q >> 1) << 3);
                    if (col > row) v = -1e30f;
                }
                s[nt][q] = v;
            }
        }
        float mx0 = -1e30f, mx1 = -1e30f;
#pragma unroll
        for (int nt = 0; nt < 8; nt++) {
            mx0 = fmaxf(mx0, fmaxf(s[nt][0], s[nt][1]));
            mx1 = fmaxf(mx1, fmaxf(s[nt][2], s[nt][3]));
        }
        mx0 = fmaxf(mx0, __shfl_xor_sync(0xffffffffu, mx0, 1));
        mx0 = fmaxf(mx0, __shfl_xor_sync(0xffffffffu, mx0, 2));
        mx1 = fmaxf(mx1, __shfl_xor_sync(0xffffffffu, mx1, 1));
        mx1 = fmaxf(mx1, __shfl_xor_sync(0xffffffffu, mx1, 2));

        float mn0 = fmaxf(m0, mx0), mn1 = fmaxf(m1, mx1);
        float al0 = __expf(m0 - mn0), al1 = __expf(m1 - mn1);
        m0 = mn0; m1 = mn1;
        float rs0 = 0.f, rs1 = 0.f;
#pragma unroll
        for (int nt = 0; nt < 8; nt++) {
            float p0 = __expf(s[nt][0] - mn0);
            float p1 = __expf(s[nt][1] - mn0);
            float p2 = __expf(s[nt][2] - mn1);
            float p3 = __expf(s[nt][3] - mn1);
            s[nt][0] = p0; s[nt][1] = p1; s[nt][2] = p2; s[nt][3] = p3;
            rs0 += p0 + p1; rs1 += p2 + p3;
        }
        rs0 += __shfl_xor_sync(0xffffffffu, rs0, 1);
        rs0 += __shfl_xor_sync(0xffffffffu, rs0, 2);
        rs1 += __shfl_xor_sync(0xffffffffu, rs1, 1);
        rs1 += __shfl_xor_sync(0xffffffffu, rs1, 2);
        l0 = l0 * al0 + rs0;
        l1 = l1 * al1 + rs1;
#pragma unroll
        for (int ct = 0; ct < 16; ct++) {
            o[ct][0] *= al0; o[ct][1] *= al0;
            o[ct][2] *= al1; o[ct][3] *= al1;
        }

        // ---- O += P V (3 split terms) ----
#pragma unroll
        for (int kj = 0; kj < 4; kj++) {
            uint32_t ph[4], pl[4];
            ph[0] = pack_hl(s[2 * kj][0],     s[2 * kj][1],     pl[0]);
            ph[1] = pack_hl(s[2 * kj][2],     s[2 * kj][3],     pl[1]);
            ph[2] = pack_hl(s[2 * kj + 1][0], s[2 * kj + 1][1], pl[2]);
            ph[3] = pack_hl(s[2 * kj + 1][2], s[2 * kj + 1][3], pl[3]);
            uint32_t vbase = Kb + (kj * 16 + vrowl) * FROW + vcof;
#pragma unroll
            for (int cp2 = 0; cp2 < 8; cp2++) {
                uint32_t vh[4], vl[4];
                uint32_t va = vbase + cp2 * 32;
                ldsm_x4t(vh, va + FV_HI);
                ldsm_x4t(vl, va + FV_LO);
                mma16816(o[2 * cp2],     ph, vh);
                mma16816(o[2 * cp2],     pl, vh);
                mma16816(o[2 * cp2],     ph, vl);
                mma16816(o[2 * cp2 + 1], ph, vh + 2);
                mma16816(o[2 * cp2 + 1], pl, vh + 2);
                mma16816(o[2 * cp2 + 1], ph, vl + 2);
            }
        }

        __syncthreads();   // all warps done reading this stage before overwrite
        if (kt + 2 < nkt) load_kv(kt + 2, kt & 1);
    }

    // ---- epilogue: normalize, split, store hi/lo ----
    float inv0 = 1.0f / l0, inv1 = 1.0f / l1;
    size_t trow0 = (size_t)b * SLEN + qt * 128 + wid * 16 + (lane >> 2);
    int colb = h * HDIM + (lane & 3) * 2;
#pragma unroll
    for (int ct = 0; ct < 16; ct++) {
        int col = colb + ct * 8;
        uint32_t lo0, lo1;
        uint32_t hi0 = pack_hl(o[ct][0] * inv0, o[ct][1] * inv0, lo0);
        uint32_t hi1 = pack_hl(o[ct][2] * inv1, o[ct][3] * inv1, lo1);
        *(uint32_t*)(ohi_g + trow0 * DMODEL + col)       = hi0;
        *(uint32_t*)(olo_g + trow0 * DMODEL + col)       = lo0;
        *(uint32_t*)(ohi_g + (trow0 + 8) * DMODEL + col) = hi1;
        *(uint32_t*)(olo_g + (trow0 + 8) * DMODEL + col) = lo1;
    }
}

// ---------------------------------------------------------------------------
// Launch. inputs: 0=x 1=mask(all-true) 2=cos 3=sin 4=wq 5=wk 6=wv 7=wo
// ---------------------------------------------------------------------------
extern "C" void kernel_launch(void* const* d_in, const int* in_sizes, int n_in,
                              void* d_out, int out_size)
{
    const float* x    = (const float*)d_in[0];
    const float* cosp = (const float*)d_in[2];
    const float* sinp = (const float*)d_in[3];
    const float* wq   = (const float*)d_in[4];
    const float* wk   = (const float*)d_in[5];
    const float* wv   = (const float*)d_in[6];
    const float* wo   = (const float*)d_in[7];
    float* outp = (float*)d_out;

    __nv_bfloat16 *xhi, *xlo, *whi, *wlo, *wohi, *wolo, *qkvhi, *qkvlo, *ahi, *alo;
    cudaGetSymbolAddress((void**)&xhi,   g_xhi);
    cudaGetSymbolAddress((void**)&xlo,   g_xlo);
    cudaGetSymbolAddress((void**)&whi,   g_whi);
    cudaGetSymbolAddress((void**)&wlo,   g_wlo);
    cudaGetSymbolAddress((void**)&wohi,  g_wohi);
    cudaGetSymbolAddress((void**)&wolo,  g_wolo);
    cudaGetSymbolAddress((void**)&qkvhi, g_qkvhi);
    cudaGetSymbolAddress((void**)&qkvlo, g_qkvlo);
    cudaGetSymbolAddress((void**)&ahi,   g_ahi);
    cudaGetSymbolAddress((void**)&alo,   g_alo);

    cudaFuncSetAttribute(gemm_mma_split, cudaFuncAttributeMaxDynamicSharedMemorySize, GSMEM);
    cudaFuncSetAttribute(flash_mma, cudaFuncAttributeMaxDynamicSharedMemorySize, FSMEM);

    const int NX = NTOK * DMODEL;
    const int NW = DMODEL * DMODEL;
    const int NK = NKVH * HDIM * DMODEL;
    split_bf16<<<NX / 1024, 256>>>(x,  xhi,  xlo,  NX);
    split_bf16<<<NW / 1024, 256>>>(wq, whi,  wlo,  NW);
    split_bf16<<<NK / 1024, 256>>>(wk, whi + (size_t)4096 * DMODEL, wlo + (size_t)4096 * DMODEL, NK);
    split_bf16<<<NK / 1024, 256>>>(wv, whi + (size_t)5120 * DMODEL, wlo + (size_t)5120 * DMODEL, NK);
    split_bf16<<<NW / 1024, 256>>>(wo, wohi, wolo, NW);

    // Fused QKV projection -> hi/lo bf16 directly
    gemm_mma_split<<<dim3(NTOK / 128, QKVW / 128), 256, GSMEM>>>(
        xhi, xlo, whi, wlo, nullptr, qkvhi, qkvlo, DMODEL, QKVW);

    // RoPE in hi/lo domain on q and k
    rope_hl<<<(NTOK * 40 * 64) / 256, 256>>>(qkvhi, qkvlo, cosp, sinp);

    // Tensor-core causal GQA attention -> ahi/alo
    flash_mma<<<dim3(SLEN / 128, NHEAD, BATCH), 256, FSMEM>>>(qkvhi, qkvlo, ahi, alo);

    // Output projection -> fp32 d_out
    gemm_mma_split<<<dim3(NTOK / 128, DMODEL / 128), 256, GSMEM>>>(
        ahi, alo, wohi, wolo, outp, nullptr, nullptr, DMODEL, DMODEL);
}

// round 7
// speedup vs baseline: 3.1818x; 1.0460x over previous
#include <cuda_runtime.h>
#include <cuda_bf16.h>
#include <cstdint>

// Problem constants
#define BATCH 2
#define SLEN  2048
#define DMODEL 4096
#define NHEAD 32
#define NKVH  8
#define HDIM  128
#define NTOK  (BATCH*SLEN)          // 4096
#define QKVW  6144                  // 4096 q + 1024 k + 1024 v
#define ATT_SCALE 0.08838834764831845f

// ---------------------------------------------------------------------------
// Scratch (allocation-free rule: __device__ globals)
// ---------------------------------------------------------------------------
__device__ __nv_bfloat16 g_xhi[(size_t)NTOK * DMODEL];
__device__ __nv_bfloat16 g_xlo[(size_t)NTOK * DMODEL];
__device__ __nv_bfloat16 g_whi[(size_t)QKVW * DMODEL];   // fused wq|wk|wv rows
__device__ __nv_bfloat16 g_wlo[(size_t)QKVW * DMODEL];
__device__ __nv_bfloat16 g_wohi[(size_t)DMODEL * DMODEL];
__device__ __nv_bfloat16 g_wolo[(size_t)DMODEL * DMODEL];
__device__ __nv_bfloat16 g_qkvhi[(size_t)NTOK * QKVW];
__device__ __nv_bfloat16 g_qkvlo[(size_t)NTOK * QKVW];
__device__ __nv_bfloat16 g_ahi[(size_t)NTOK * DMODEL];
__device__ __nv_bfloat16 g_alo[(size_t)NTOK * DMODEL];

// ---------------------------------------------------------------------------
// Helpers
// ---------------------------------------------------------------------------
__device__ __forceinline__ uint32_t smem_u32(const void* p) {
    uint32_t a;
    asm("{ .reg .u64 t; cvta.to.shared.u64 t, %1; cvt.u32.u64 %0, t; }" : "=r"(a) : "l"(p));
    return a;
}
__device__ __forceinline__ void cp16(uint32_t dst, const void* src) {
    asm volatile("cp.async.cg.shared.global [%0], [%1], 16;" :: "r"(dst), "l"(src));
}
__device__ __forceinline__ void ldsm_x4(uint32_t* r, uint32_t addr) {
    asm volatile("ldmatrix.sync.aligned.m8n8.x4.shared.b16 {%0,%1,%2,%3}, [%4];"
                 : "=r"(r[0]), "=r"(r[1]), "=r"(r[2]), "=r"(r[3]) : "r"(addr));
}
__device__ __forceinline__ void ldsm_x4t(uint32_t* r, uint32_t addr) {
    asm volatile("ldmatrix.sync.aligned.m8n8.x4.trans.shared.b16 {%0,%1,%2,%3}, [%4];"
                 : "=r"(r[0]), "=r"(r[1]), "=r"(r[2]), "=r"(r[3]) : "r"(addr));
}
__device__ __forceinline__ void mma16816(float* d, const uint32_t* a, const uint32_t* b) {
    asm volatile("mma.sync.aligned.m16n8k16.row.col.f32.bf16.bf16.f32 "
                 "{%0,%1,%2,%3}, {%4,%5,%6,%7}, {%8,%9}, {%0,%1,%2,%3};"
                 : "+f"(d[0]), "+f"(d[1]), "+f"(d[2]), "+f"(d[3])
                 : "r"(a[0]), "r"(a[1]), "r"(a[2]), "r"(a[3]), "r"(b[0]), "r"(b[1]));
}
// split fp32 pair -> (hi u32 bf16x2, lo u32 bf16x2)
__device__ __forceinline__ uint32_t pack_hl(float f0, float f1, uint32_t& lo) {
    __nv_bfloat16 h0 = __float2bfloat16(f0), h1 = __float2bfloat16(f1);
    __nv_bfloat16 l0 = __float2bfloat16(f0 - __bfloat162float(h0));
    __nv_bfloat16 l1 = __float2bfloat16(f1 - __bfloat162float(h1));
    __nv_bfloat162 hp(h0, h1), lp(l0, l1);
    lo = *(uint32_t*)&lp;
    return *(uint32_t*)&hp;
}

// ---------------------------------------------------------------------------
// bf16 split HGEMM via mma.sync:
// C = Ahi*Bhi^T + Ahi*Blo^T + Alo*Bhi^T.  Epilogue: fp32 C, or hi/lo split.
// CTA 128x256, BK=32, 8 warps (warp tile 64x64), 3-stage cp.async pipeline.
// grid: (M/128, N/256), 256 threads.
// ---------------------------------------------------------------------------
#define ROWB   80
#define A_ROWS 128
#define B_ROWS 256
#define ABUF   (A_ROWS * ROWB)          // 10240
#define BBUF   (B_ROWS * ROWB)          // 20480
#define STAGEB (2 * ABUF + 2 * BBUF)    // 61440
#define NSTAGE 3
#define GSMEM  (NSTAGE * STAGEB)        // 184320 B

__global__ __launch_bounds__(256, 1) void gemm_mma_split(
    const __nv_bfloat16* __restrict__ Ahi, const __nv_bfloat16* __restrict__ Alo,
    const __nv_bfloat16* __restrict__ Bhi, const __nv_bfloat16* __restrict__ Blo,
    float* __restrict__ C, __nv_bfloat16* __restrict__ Chi, __nv_bfloat16* __restrict__ Clo,
    int K, int ldc)
{
    extern __shared__ char dynsm[];
    const uint32_t smb = smem_u32(dynsm);
    const int tid  = threadIdx.x;
    const int wid  = tid >> 5;
    const int lane = tid & 31;
    const int m0 = blockIdx.x * 128;
    const int n0 = blockIdx.y * 256;
    const int nch = K >> 5;

    auto load_stage = [&](int c, int st) {
        const uint32_t sb = smb + st * STAGEB;
        // A hi/lo: 128 rows x 64B, 2 iters of 256 threads each
#pragma unroll
        for (int i = 0; i < 2; i++) {
            int o = i * 256 + tid;
            int r = o >> 2, s = o & 3;
            size_t go = (size_t)(m0 + r) * K + c * 32 + s * 8;
            uint32_t so = r * ROWB + s * 16;
            cp16(sb + so,        Ahi + go);
            cp16(sb + ABUF + so, Alo + go);
        }
        // B hi/lo: 256 rows x 64B, 4 iters
#pragma unroll
        for (int i = 0; i < 4; i++) {
            int o = i * 256 + tid;
            int r = o >> 2, s = o & 3;
            size_t go = (size_t)(n0 + r) * K + c * 32 + s * 8;
            uint32_t so = r * ROWB + s * 16;
            cp16(sb + 2 * ABUF + so,        Bhi + go);
            cp16(sb + 2 * ABUF + BBUF + so, Blo + go);
        }
        asm volatile("cp.async.commit_group;" ::: "memory");
    };

    float acc[4][8][4];
#pragma unroll
    for (int mt = 0; mt < 4; mt++)
#pragma unroll
        for (int nt = 0; nt < 8; nt++)
#pragma unroll
            for (int q = 0; q < 4; q++) acc[mt][nt][q] = 0.f;

    load_stage(0, 0);
    load_stage(1, 1);

    const int wm = (wid >> 2) * 64;            // 0 or 64
    const int wn = (wid & 3) * 64;             // 0,64,128,192
    // A x4 pattern (validated R5): rows lane&15, col-half lane>>4
    const int arow = lane & 15, acolg = lane >> 4;
    // B x4 pattern (validated R6 flash): row ((lane>>4)<<3)+(lane&7), k-half ((lane>>3)&1)
    const int brow = ((lane >> 4) << 3) + (lane & 7);
    const int bkof = ((lane >> 3) & 1) * 16;

    for (int c = 0; c < nch; c++) {
        // pending groups here: {c, c+1}; wait_group 1 -> stage c resident
        if (c + 1 < nch) asm volatile("cp.async.wait_group 1;" ::: "memory");
        else             asm volatile("cp.async.wait_group 0;" ::: "memory");
        __syncthreads();
        // WAR-safe: buffer (c+2)%3 was last read in compute c-1 (before this barrier)
        if (c + 2 < nch) load_stage(c + 2, (c + 2) % NSTAGE);

        const uint32_t sb   = smb + (c % NSTAGE) * STAGEB;
        const uint32_t aHiB = sb;
        const uint32_t aLoB = sb + ABUF;
        const uint32_t bHiB = sb + 2 * ABUF;
        const uint32_t bLoB = sb + 2 * ABUF + BBUF;

#pragma unroll
        for (int ks = 0; ks < 2; ks++) {
            const int kb = ks * 32;
            uint32_t ah[4][4], al[4][4];
#pragma unroll
            for (int mt = 0; mt < 4; mt++) {
                uint32_t ao = (wm + mt * 16 + arow) * ROWB + kb + acolg * 16;
                ldsm_x4(ah[mt], aHiB + ao);
                ldsm_x4(al[mt], aLoB + ao);
            }
#pragma unroll
            for (int nt = 0; nt < 4; nt++) {
                uint32_t bh[4], bl[4];
                uint32_t bo = (wn + nt * 16 + brow) * ROWB + kb + bkof;
                ldsm_x4(bh, bHiB + bo);
                ldsm_x4(bl, bLoB + bo);
#pragma unroll
                for (int mt = 0; mt < 4; mt++) mma16816(acc[mt][2 * nt],     ah[mt], bh);
#pragma unroll
                for (int mt = 0; mt < 4; mt++) mma16816(acc[mt][2 * nt],     ah[mt], bl);
#pragma unroll
                for (int mt = 0; mt < 4; mt++) mma16816(acc[mt][2 * nt],     al[mt], bh);
#pragma unroll
                for (int mt = 0; mt < 4; mt++) mma16816(acc[mt][2 * nt + 1], ah[mt], bh + 2);
#pragma unroll
                for (int mt = 0; mt < 4; mt++) mma16816(acc[mt][2 * nt + 1], ah[mt], bl + 2);
#pragma unroll
                for (int mt = 0; mt < 4; mt++) mma16816(acc[mt][2 * nt + 1], al[mt], bh + 2);
            }
        }
    }

#pragma unroll
    for (int mt = 0; mt < 4; mt++) {
        int r0 = m0 + wm + mt * 16 + (lane >> 2);
#pragma unroll
        for (int nt = 0; nt < 8; nt++) {
            int cc = n0 + wn + nt * 8 + (lane & 3) * 2;
            if (Chi) {
                uint32_t lo0, lo1;
                uint32_t hi0 = pack_hl(acc[mt][nt][0], acc[mt][nt][1], lo0);
                uint32_t hi1 = pack_hl(acc[mt][nt][2], acc[mt][nt][3], lo1);
                *(uint32_t*)(Chi + (size_t)r0 * ldc + cc)       = hi0;
                *(uint32_t*)(Clo + (size_t)r0 * ldc + cc)       = lo0;
                *(uint32_t*)(Chi + (size_t)(r0 + 8) * ldc + cc) = hi1;
                *(uint32_t*)(Clo + (size_t)(r0 + 8) * ldc + cc) = lo1;
            } else {
                *(float2*)(C + (size_t)r0 * ldc + cc)       = make_float2(acc[mt][nt][0], acc[mt][nt][1]);
                *(float2*)(C + (size_t)(r0 + 8) * ldc + cc) = make_float2(acc[mt][nt][2], acc[mt][nt][3]);
            }
        }
    }
}

// ---------------------------------------------------------------------------
// fp32 -> bf16 hi/lo split (4 elems/thread)
// ---------------------------------------------------------------------------
__global__ void split_bf16(const float* __restrict__ src,
                           __nv_bfloat16* __restrict__ hi,
                           __nv_bfloat16* __restrict__ lo, int n)
{
    int i = (blockIdx.x * 256 + threadIdx.x) * 4;
    if (i >= n) return;
    float4 v = *(const float4*)(src + i);
    uint32_t l0, l1;
    uint32_t h0 = pack_hl(v.x, v.y, l0);
    uint32_t h1 = pack_hl(v.z, v.w, l1);
    *(uint2*)(hi + i) = make_uint2(h0, h1);
    *(uint2*)(lo + i) = make_uint2(l0, l1);
}

// ---------------------------------------------------------------------------
// RoPE on hi/lo representation, in place on q + k of g_qkvhi/g_qkvlo
// ---------------------------------------------------------------------------
__global__ void rope_hl(__nv_bfloat16* __restrict__ hi, __nv_bfloat16* __restrict__ lo,
                        const float* __restrict__ cosp, const float* __restrict__ sinp)
{
    int idx = blockIdx.x * 256 + threadIdx.x;
    if (idx >= NTOK * 40 * 64) return;
    int p  = idx & 63;
    int h2 = (idx >> 6) % 40;
    int t  = idx / (64 * 40);
    float c  = cosp[(size_t)t * 64 + p];
    float sn = sinp[(size_t)t * 64 + p];
    size_t base = (size_t)t * QKVW + (h2 < 32 ? h2 * HDIM : 4096 + (h2 - 32) * HDIM) + 2 * p;
    float t0 = __bfloat162float(hi[base])     + __bfloat162float(lo[base]);
    float t1 = __bfloat162float(hi[base + 1]) + __bfloat162float(lo[base + 1]);
    float r0 = t0 * c - t1 * sn;
    float r1 = t0 * sn + t1 * c;
    uint32_t lp;
    uint32_t hp = pack_hl(r0, r1, lp);
    *(uint32_t*)(hi + base) = hp;
    *(uint32_t*)(lo + base) = lp;
}

// ---------------------------------------------------------------------------
// Flash attention, tensor-core (bf16 3-term split), causal, GQA 4:1.
// (unchanged from R6 — known correct)
// ---------------------------------------------------------------------------
#define FROW    272
#define FQLO    (128 * FROW)
#define FSTAGE0 (2 * 128 * FROW)
#define FSTAGESZ (4 * 64 * FROW)
#define FK_HI 0
#define FK_LO (64 * FROW)
#define FV_HI (2 * 64 * FROW)
#define FV_LO (3 * 64 * FROW)
#define FSMEM (FSTAGE0 + 2 * FSTAGESZ)   // 208896 B

__global__ __launch_bounds__(256, 1) void flash_mma(
    const __nv_bfloat16* __restrict__ qhi, const __nv_bfloat16* __restrict__ qlo,
    __nv_bfloat16* __restrict__ ohi_g, __nv_bfloat16* __restrict__ olo_g)
{
    extern __shared__ char fsm[];
    const uint32_t smb = smem_u32(fsm);
    const int qt = 15 - (int)blockIdx.x;
    const int h  = blockIdx.y;
    const int b  = blockIdx.z;
    const int kvh = h >> 2;
    const int tid = threadIdx.x, wid = tid >> 5, lane = tid & 31;
    const int nkt = 2 * qt + 2;

    const size_t tokQ = (size_t)b * SLEN + (size_t)qt * 128;
    const __nv_bfloat16* Qhg = qhi + tokQ * QKVW + h * HDIM;
    const __nv_bfloat16* Qlg = qlo + tokQ * QKVW + h * HDIM;
    const size_t kvbase = (size_t)b * SLEN * QKVW + kvh * HDIM;
    const __nv_bfloat16* Khg = qhi + kvbase + 4096;
    const __nv_bfloat16* Klg = qlo + kvbase + 4096;
    const __nv_bfloat16* Vhg = qhi + kvbase + 5120;
    const __nv_bfloat16* Vlg = qlo + kvbase + 5120;

    auto load_kv = [&](int kt, int buf) {
        const uint32_t sb = smb + FSTAGE0 + buf * FSTAGESZ;
#pragma unroll
        for (int i = 0; i < 4; i++) {
            int ch = tid + i * 256;
            int r = ch >> 4, s = ch & 15;
            size_t go = (size_t)(kt * 64 + r) * QKVW + s * 8;
            uint32_t so = r * FROW + s * 16;
            cp16(sb + FK_HI + so, Khg + go);
            cp16(sb + FK_LO + so, Klg + go);
            cp16(sb + FV_HI + so, Vhg + go);
            cp16(sb + FV_LO + so, Vlg + go);
        }
        asm volatile("cp.async.commit_group;" ::: "memory");
    };

#pragma unroll
    for (int i = 0; i < 8; i++) {
        int ch = tid + i * 256;
        int r = ch >> 4, s = ch & 15;
        size_t go = (size_t)r * QKVW + s * 8;
        uint32_t so = r * FROW + s * 16;
        cp16(smb + so,        Qhg + go);
        cp16(smb + FQLO + so, Qlg + go);
    }
    load_kv(0, 0);
    load_kv(1, 1);

    float o[16][4];
#pragma unroll
    for (int ct = 0; ct < 16; ct++)
#pragma unroll
        for (int q = 0; q < 4; q++) o[ct][q] = 0.f;
    float m0 = -1e30f, m1 = -1e30f, l0 = 0.f, l1 = 0.f;

    const uint32_t aAddr0 = smb + (wid * 16 + (lane & 15)) * FROW + (lane >> 4) * 16;
    const int brow = ((lane >> 4) << 3) + (lane & 7);
    const int bkof = ((lane >> 3) & 1) * 16;
    const int vrowl = ((lane >> 3) & 1) * 8 + (lane & 7);
    const int vcof = ((lane >> 4) << 3) * 2;

    for (int kt = 0; kt < nkt; kt++) {
        if (kt + 1 < nkt) asm volatile("cp.async.wait_group 1;" ::: "memory");
        else              asm volatile("cp.async.wait_group 0;" ::: "memory");
        __syncthreads();

        const uint32_t Kb = smb + FSTAGE0 + (kt & 1) * FSTAGESZ;

        float s[8][4];
#pragma unroll
        for (int nt = 0; nt < 8; nt++)
#pragma unroll
            for (int q = 0; q < 4; q++) s[nt][q] = 0.f;

#pragma unroll
        for (int ks = 0; ks < 8; ks++) {
            uint32_t ah[4], al[4];
            ldsm_x4(ah, aAddr0 + ks * 32);
            ldsm_x4(al, aAddr0 + FQLO + ks * 32);
#pragma unroll
            for (int np = 0; np < 4; np++) {
                uint32_t bh[4], bl[4];
                uint32_t ba = Kb + (np * 16 + brow) * FROW + ks * 32 + bkof;
                ldsm_x4(bh, ba + FK_HI);
                ldsm_x4(bl, ba + FK_LO);
                mma16816(s[2 * np],     ah, bh);
                mma16816(s[2 * np],     ah, bl);
                mma16816(s[2 * np],     al, bh);
                mma16816(s[2 * np + 1], ah, bh + 2);
                mma16816(s[2 * np + 1], ah, bl + 2);
                mma16816(s[2 * np + 1], al, bh + 2);
            }
        }

        const bool need_mask = (kt >= 2 * qt);
        const int rg0 = qt * 128 + wid * 16 + (lane >> 2);
#pragma unroll
        for (int nt = 0; nt < 8; nt++) {
#pragma unroll
            for (int q = 0; q < 4; q++) {
                float v = s[nt][q] * ATT_SCALE;
                if (need_mask) {
                    int col = kt * 64 + nt * 8 + (lane & 3) * 2 + (q & 1);
                    int row = rg0 + ((q >> 1) << 3);
                    if (col > row) v = -1e30f;
                }
                s[nt][q] = v;
            }
        }
        float mx0 = -1e30f, mx1 = -1e30f;
#pragma unroll
        for (int nt = 0; nt < 8; nt++) {
            mx0 = fmaxf(mx0, fmaxf(s[nt][0], s[nt][1]));
            mx1 = fmaxf(mx1, fmaxf(s[nt][2], s[nt][3]));
        }
        mx0 = fmaxf(mx0, __shfl_xor_sync(0xffffffffu, mx0, 1));
        mx0 = fmaxf(mx0, __shfl_xor_sync(0xffffffffu, mx0, 2));
        mx1 = fmaxf(mx1, __shfl_xor_sync(0xffffffffu, mx1, 1));
        mx1 = fmaxf(mx1, __shfl_xor_sync(0xffffffffu, mx1, 2));

        float mn0 = fmaxf(m0, mx0), mn1 = fmaxf(m1, mx1);
        float al0 = __expf(m0 - mn0), al1 = __expf(m1 - mn1);
        m0 = mn0; m1 = mn1;
        float rs0 = 0.f, rs1 = 0.f;
#pragma unroll
        for (int nt = 0; nt < 8; nt++) {
            float p0 = __expf(s[nt][0] - mn0);
            float p1 = __expf(s[nt][1] - mn0);
            float p2 = __expf(s[nt][2] - mn1);
            float p3 = __expf(s[nt][3] - mn1);
            s[nt][0] = p0; s[nt][1] = p1; s[nt][2] = p2; s[nt][3] = p3;
            rs0 += p0 + p1; rs1 += p2 + p3;
        }
        rs0 += __shfl_xor_sync(0xffffffffu, rs0, 1);
        rs0 += __shfl_xor_sync(0xffffffffu, rs0, 2);
        rs1 += __shfl_xor_sync(0xffffffffu, rs1, 1);
        rs1 += __shfl_xor_sync(0xffffffffu, rs1, 2);
        l0 = l0 * al0 + rs0;
        l1 = l1 * al1 + rs1;
#pragma unroll
        for (int ct = 0; ct < 16; ct++) {
            o[ct][0] *= al0; o[ct][1] *= al0;
            o[ct][2] *= al1; o[ct][3] *= al1;
        }

#pragma unroll
        for (int kj = 0; kj < 4; kj++) {
            uint32_t ph[4], pl[4];
            ph[0] = pack_hl(s[2 * kj][0],     s[2 * kj][1],     pl[0]);
            ph[1] = pack_hl(s[2 * kj][2],     s[2 * kj][3],     pl[1]);
            ph[2] = pack_hl(s[2 * kj + 1][0], s[2 * kj + 1][1], pl[2]);
            ph[3] = pack_hl(s[2 * kj + 1][2], s[2 * kj + 1][3], pl[3]);
            uint32_t vbase = Kb + (kj * 16 + vrowl) * FROW + vcof;
#pragma unroll
            for (int cp2 = 0; cp2 < 8; cp2++) {
                uint32_t vh[4], vl[4];
                uint32_t va = vbase + cp2 * 32;
                ldsm_x4t(vh, va + FV_HI);
                ldsm_x4t(vl, va + FV_LO);
                mma16816(o[2 * cp2],     ph, vh);
                mma16816(o[2 * cp2],     pl, vh);
                mma16816(o[2 * cp2],     ph, vl);
                mma16816(o[2 * cp2 + 1], ph, vh + 2);
                mma16816(o[2 * cp2 + 1], pl, vh + 2);
                mma16816(o[2 * cp2 + 1], ph, vl + 2);
            }
        }

        __syncthreads();
        if (kt + 2 < nkt) load_kv(kt + 2, kt & 1);
    }

    float inv0 = 1.0f / l0, inv1 = 1.0f / l1;
    size_t trow0 = (size_t)b * SLEN + qt * 128 + wid * 16 + (lane >> 2);
    int colb = h * HDIM + (lane & 3) * 2;
#pragma unroll
    for (int ct = 0; ct < 16; ct++) {
        int col = colb + ct * 8;
        uint32_t lo0, lo1;
        uint32_t hi0 = pack_hl(o[ct][0] * inv0, o[ct][1] * inv0, lo0);
        uint32_t hi1 = pack_hl(o[ct][2] * inv1, o[ct][3] * inv1, lo1);
        *(uint32_t*)(ohi_g + trow0 * DMODEL + col)       = hi0;
        *(uint32_t*)(olo_g + trow0 * DMODEL + col)       = lo0;
        *(uint32_t*)(ohi_g + (trow0 + 8) * DMODEL + col) = hi1;
        *(uint32_t*)(olo_g + (trow0 + 8) * DMODEL + col) = lo1;
    }
}

// ---------------------------------------------------------------------------
// Launch. inputs: 0=x 1=mask(all-true) 2=cos 3=sin 4=wq 5=wk 6=wv 7=wo
// ---------------------------------------------------------------------------
extern "C" void kernel_launch(void* const* d_in, const int* in_sizes, int n_in,
                              void* d_out, int out_size)
{
    const float* x    = (const float*)d_in[0];
    const float* cosp = (const float*)d_in[2];
    const float* sinp = (const float*)d_in[3];
    const float* wq   = (const float*)d_in[4];
    const float* wk   = (const float*)d_in[5];
    const float* wv   = (const float*)d_in[6];
    const float* wo   = (const float*)d_in[7];
    float* outp = (float*)d_out;

    __nv_bfloat16 *xhi, *xlo, *whi, *wlo, *wohi, *wolo, *qkvhi, *qkvlo, *ahi, *alo;
    cudaGetSymbolAddress((void**)&xhi,   g_xhi);
    cudaGetSymbolAddress((void**)&xlo,   g_xlo);
    cudaGetSymbolAddress((void**)&whi,   g_whi);
    cudaGetSymbolAddress((void**)&wlo,   g_wlo);
    cudaGetSymbolAddress((void**)&wohi,  g_wohi);
    cudaGetSymbolAddress((void**)&wolo,  g_wolo);
    cudaGetSymbolAddress((void**)&qkvhi, g_qkvhi);
    cudaGetSymbolAddress((void**)&qkvlo, g_qkvlo);
    cudaGetSymbolAddress((void**)&ahi,   g_ahi);
    cudaGetSymbolAddress((void**)&alo,   g_alo);

    cudaFuncSetAttribute(gemm_mma_split, cudaFuncAttributeMaxDynamicSharedMemorySize, GSMEM);
    cudaFuncSetAttribute(flash_mma, cudaFuncAttributeMaxDynamicSharedMemorySize, FSMEM);

    const int NX = NTOK * DMODEL;
    const int NW = DMODEL * DMODEL;
    const int NK = NKVH * HDIM * DMODEL;
    split_bf16<<<NX / 1024, 256>>>(x,  xhi,  xlo,  NX);
    split_bf16<<<NW / 1024, 256>>>(wq, whi,  wlo,  NW);
    split_bf16<<<NK / 1024, 256>>>(wk, whi + (size_t)4096 * DMODEL, wlo + (size_t)4096 * DMODEL, NK);
    split_bf16<<<NK / 1024, 256>>>(wv, whi + (size_t)5120 * DMODEL, wlo + (size_t)5120 * DMODEL, NK);
    split_bf16<<<NW / 1024, 256>>>(wo, wohi, wolo, NW);

    // Fused QKV projection -> hi/lo bf16 directly
    gemm_mma_split<<<dim3(NTOK / 128, QKVW / 256), 256, GSMEM>>>(
        xhi, xlo, whi, wlo, nullptr, qkvhi, qkvlo, DMODEL, QKVW);

    // RoPE in hi/lo domain on q and k
    rope_hl<<<(NTOK * 40 * 64) / 256, 256>>>(qkvhi, qkvlo, cosp, sinp);

    // Tensor-core causal GQA attention -> ahi/alo
    flash_mma<<<dim3(SLEN / 128, NHEAD, BATCH), 256, FSMEM>>>(qkvhi, qkvlo, ahi, alo);

    // Output projection -> fp32 d_out
    gemm_mma_split<<<dim3(NTOK / 128, DMODEL / 256), 256, GSMEM>>>(
        ahi, alo, wohi, wolo, outp, nullptr, nullptr, DMODEL, DMODEL);
}